// round 1
// baseline (speedup 1.0000x reference)
#include <cuda_runtime.h>
#include <cuda_bf16.h>
#include <cstdint>

// ---------------- problem constants ----------------
#define BB   32
#define HH   56
#define CC   192
#define LL   (HH*HH)           // 3136
#define NHD  6
#define HD   32
#define WSZ  7
#define SSH  3
#define NWIN 49                // tokens per window
#define NWX  8                 // windows per axis
#define NWTOT 64               // windows per image
#define BW   (BB*NWTOT)        // 2048 windows total
#define MROWS (BW*NWIN)        // 100352 token rows
#define HID  768
#define QSCALE 0.17677669529663687f   // 32^-0.5

// ---------------- scratch (device globals; allocation-free rule) ----------
__device__ float g_xw [(size_t)MROWS*CC];    // LN1-gathered windows; reused for LN2 output
__device__ float g_qkv[(size_t)MROWS*3*CC];  // qkv
__device__ float g_o  [(size_t)MROWS*CC];    // attention output (window layout)
__device__ float g_h1 [(size_t)MROWS*HID];   // MLP hidden

// window-row m  ->  global token row (b*3136 + i0*56 + j0) with unshift (+3 mod 56)
__device__ __forceinline__ int remap_row(int m) {
    int w = m / NWIN, n = m - w * NWIN;
    int b = w >> 6, widx = w & 63;
    int wi = widx >> 3, wj = widx & 7;
    int ti = n / WSZ, tj = n - ti * WSZ;
    int i0 = wi * WSZ + ti + SSH; if (i0 >= HH) i0 -= HH;
    int j0 = wj * WSZ + tj + SSH; if (j0 >= HH) j0 -= HH;
    return b * LL + i0 * HH + j0;
}

// ---------------- LayerNorm (one block per row, 192 threads) ----------------
template<bool GATHER>
__global__ void ln_kernel(const float* __restrict__ x, const float* __restrict__ g,
                          const float* __restrict__ b, float* __restrict__ y) {
    int m = blockIdx.x;
    int r = GATHER ? remap_row(m) : m;
    int tid = threadIdx.x;                 // 0..191
    float val = x[(size_t)r * CC + tid];
    float s = val, s2 = val * val;
    #pragma unroll
    for (int off = 16; off; off >>= 1) {
        s  += __shfl_xor_sync(~0u, s,  off);
        s2 += __shfl_xor_sync(~0u, s2, off);
    }
    __shared__ float red[12];
    int warp = tid >> 5, lane = tid & 31;
    if (lane == 0) { red[warp] = s; red[6 + warp] = s2; }
    __syncthreads();
    if (tid < 32) {
        float a = (tid < 6) ? red[tid]     : 0.f;
        float c = (tid < 6) ? red[6 + tid] : 0.f;
        #pragma unroll
        for (int off = 4; off; off >>= 1) {
            a += __shfl_xor_sync(~0u, a, off);
            c += __shfl_xor_sync(~0u, c, off);
        }
        if (tid == 0) { red[0] = a; red[1] = c; }
    }
    __syncthreads();
    float mean = red[0] * (1.f / CC);
    float var  = red[1] * (1.f / CC) - mean * mean;
    float inv  = rsqrtf(var + 1e-5f);
    y[(size_t)m * CC + tid] = (val - mean) * inv * g[tid] + b[tid];
}

// ---------------- tiled fp32 GEMM: C[M,N] = A[M,K] @ B[K,N] + bias --------
// EPI: 0 = qkv (scale q columns), 1 = proj (row remap + residual from resid),
//      2 = GELU (exact erf), 3 = accumulate into C
#define TBM 64
#define TBN 64
#define TBK 16

template<int EPI>
__global__ __launch_bounds__(256) void gemm_k(
    const float* __restrict__ A, const float* __restrict__ B,
    const float* __restrict__ bias, float* __restrict__ C,
    int M, int N, int K, const float* __restrict__ resid)
{
    __shared__ float As[TBK][TBM + 4];
    __shared__ float Bs[TBK][TBN + 4];
    int bm = blockIdx.y * TBM;
    int bn = blockIdx.x * TBN;
    int tid = threadIdx.x;
    int tx = tid & 15, ty = tid >> 4;

    int am  = tid >> 2;            // 0..63 (row within A tile)
    int ak  = (tid & 3) * 4;       // 0/4/8/12 (k within tile)
    int bk  = tid >> 4;            // 0..15
    int bn4 = (tid & 15) * 4;      // 0..60

    float acc[4][4] = {};
    for (int k0 = 0; k0 < K; k0 += TBK) {
        float4 av = *(const float4*)&A[(size_t)(bm + am) * K + k0 + ak];
        As[ak + 0][am] = av.x; As[ak + 1][am] = av.y;
        As[ak + 2][am] = av.z; As[ak + 3][am] = av.w;
        float4 bv = *(const float4*)&B[(size_t)(k0 + bk) * N + bn + bn4];
        *(float4*)&Bs[bk][bn4] = bv;
        __syncthreads();
        #pragma unroll
        for (int k = 0; k < TBK; k++) {
            float4 a4 = *(const float4*)&As[k][ty * 4];
            float4 b4 = *(const float4*)&Bs[k][tx * 4];
            float a[4] = {a4.x, a4.y, a4.z, a4.w};
            float b[4] = {b4.x, b4.y, b4.z, b4.w};
            #pragma unroll
            for (int i = 0; i < 4; i++)
                #pragma unroll
                for (int j = 0; j < 4; j++)
                    acc[i][j] = fmaf(a[i], b[j], acc[i][j]);
        }
        __syncthreads();
    }

    #pragma unroll
    for (int i = 0; i < 4; i++) {
        int m = bm + ty * 4 + i;
        int row = (EPI == 1) ? remap_row(m) : m;
        #pragma unroll
        for (int j = 0; j < 4; j++) {
            int n = bn + tx * 4 + j;
            float v = acc[i][j] + bias[n];
            if (EPI == 0) {                 // qkv: scale q block
                if (n < CC) v *= QSCALE;
            } else if (EPI == 1) {          // proj: residual add, scattered row
                v += resid[(size_t)row * N + n];
            } else if (EPI == 2) {          // exact-erf GELU
                v = 0.5f * v * (1.f + erff(v * 0.70710678118654752f));
            } else if (EPI == 3) {          // accumulate (second residual)
                v += C[(size_t)row * N + n];
            }
            C[(size_t)row * N + n] = v;
        }
    }
}

// ---------------- windowed attention: one block per (window, head) --------
__global__ __launch_bounds__(256) void attn_kernel(
    const float* __restrict__ qkv, const float* __restrict__ rel_table,
    const int* __restrict__ rel_index, const float* __restrict__ mask,
    float* __restrict__ o)
{
    int w = blockIdx.x;            // 0..2047
    int h = blockIdx.y;            // 0..5
    int widx = w & 63;
    int tid = threadIdx.x;         // 256 threads

    __shared__ float q[NWIN][33], k[NWIN][33], v[NWIN][33];
    __shared__ float S[NWIN][NWIN];

    const float* base = qkv + (size_t)w * NWIN * (3 * CC) + h * HD;
    for (int e = tid; e < NWIN * HD; e += 256) {
        int i = e >> 5, d = e & 31;
        q[i][d] = base[i * (3 * CC) + d];
        k[i][d] = base[i * (3 * CC) + CC + d];
        v[i][d] = base[i * (3 * CC) + 2 * CC + d];
    }
    __syncthreads();

    // scores + bias + mask
    for (int e = tid; e < NWIN * NWIN; e += 256) {
        int i = e / NWIN, j = e - i * NWIN;
        float s = 0.f;
        #pragma unroll
        for (int d = 0; d < HD; d++) s = fmaf(q[i][d], k[j][d], s);
        s += rel_table[rel_index[e] * NHD + h];
        s += mask[(size_t)widx * (NWIN * NWIN) + e];
        S[i][j] = s;
    }
    __syncthreads();

    // softmax per row (one warp per row, 8 warps)
    int warp = tid >> 5, lane = tid & 31;
    for (int i = warp; i < NWIN; i += 8) {
        float a  = S[i][lane];
        float b2 = (lane + 32 < NWIN) ? S[i][lane + 32] : -1e30f;
        float mx = fmaxf(a, b2);
        #pragma unroll
        for (int off = 16; off; off >>= 1) mx = fmaxf(mx, __shfl_xor_sync(~0u, mx, off));
        float e1 = __expf(a - mx);
        float e2 = (lane + 32 < NWIN) ? __expf(b2 - mx) : 0.f;
        float sm = e1 + e2;
        #pragma unroll
        for (int off = 16; off; off >>= 1) sm += __shfl_xor_sync(~0u, sm, off);
        float inv = 1.f / sm;
        S[i][lane] = e1 * inv;
        if (lane + 32 < NWIN) S[i][lane + 32] = e2 * inv;
    }
    __syncthreads();

    // O = P @ V, write into (Bw, N, C) layout at head offset
    float* orow = o + (size_t)w * NWIN * CC + h * HD;
    for (int e = tid; e < NWIN * HD; e += 256) {
        int i = e >> 5, d = e & 31;
        float s = 0.f;
        #pragma unroll
        for (int j = 0; j < NWIN; j++) s = fmaf(S[i][j], v[j][d], s);
        orow[i * CC + d] = s;
    }
}

// ---------------- launch ----------------
extern "C" void kernel_launch(void* const* d_in, const int* in_sizes, int n_in,
                              void* d_out, int out_size) {
    const float* x        = (const float*)d_in[0];
    const float* norm1_g  = (const float*)d_in[1];
    const float* norm1_b  = (const float*)d_in[2];
    const float* qkv_w    = (const float*)d_in[3];
    const float* qkv_b    = (const float*)d_in[4];
    const float* proj_w   = (const float*)d_in[5];
    const float* proj_b   = (const float*)d_in[6];
    const float* norm2_g  = (const float*)d_in[7];
    const float* norm2_b  = (const float*)d_in[8];
    const float* fc1_w    = (const float*)d_in[9];
    const float* fc1_b    = (const float*)d_in[10];
    const float* fc2_w    = (const float*)d_in[11];
    const float* fc2_b    = (const float*)d_in[12];
    const float* rel_table= (const float*)d_in[13];
    const int*   rel_index= (const int*)  d_in[14];
    const float* mask     = (const float*)d_in[15];
    float* out = (float*)d_out;

    float *xw, *qkv, *o, *h1;
    cudaGetSymbolAddress((void**)&xw,  g_xw);
    cudaGetSymbolAddress((void**)&qkv, g_qkv);
    cudaGetSymbolAddress((void**)&o,   g_o);
    cudaGetSymbolAddress((void**)&h1,  g_h1);

    // 1) LN1 + shift + window partition gather
    ln_kernel<true><<<MROWS, CC>>>(x, norm1_g, norm1_b, xw);
    // 2) QKV GEMM (q pre-scaled)
    gemm_k<0><<<dim3((3*CC)/TBN, MROWS/TBM), 256>>>(xw, qkv_w, qkv_b, qkv,
                                                    MROWS, 3*CC, CC, nullptr);
    // 3) windowed attention
    attn_kernel<<<dim3(BW, NHD), 256>>>(qkv, rel_table, rel_index, mask, o);
    // 4) proj + window reverse + unshift + residual  -> d_out holds x2
    gemm_k<1><<<dim3(CC/TBN, MROWS/TBM), 256>>>(o, proj_w, proj_b, out,
                                                MROWS, CC, CC, x);
    // 5) LN2 (reuse xw buffer)
    ln_kernel<false><<<MROWS, CC>>>(out, norm2_g, norm2_b, xw);
    // 6) FC1 + exact GELU
    gemm_k<2><<<dim3(HID/TBN, MROWS/TBM), 256>>>(xw, fc1_w, fc1_b, h1,
                                                 MROWS, HID, CC, nullptr);
    // 7) FC2 + accumulate into d_out
    gemm_k<3><<<dim3(CC/TBN, MROWS/TBM), 256>>>(h1, fc2_w, fc2_b, out,
                                                MROWS, CC, HID, nullptr);
}

// round 2
// speedup vs baseline: 1.6704x; 1.6704x over previous
#include <cuda_runtime.h>
#include <cuda_bf16.h>
#include <cstdint>

// ---------------- problem constants ----------------
#define BB   32
#define HH   56
#define CC   192
#define LL   (HH*HH)
#define NHD  6
#define HD   32
#define WSZ  7
#define SSH  3
#define NWIN 49
#define BW   2048
#define MROWS (BW*NWIN)        // 100352
#define HID  768
#define QSCALE 0.17677669529663687f

// ---------------- scratch ----------------
__device__ float g_xw [(size_t)MROWS*CC];
__device__ float g_qkv[(size_t)MROWS*3*CC];
__device__ float g_o  [(size_t)MROWS*CC];
__device__ float g_h1 [(size_t)MROWS*HID];

__device__ __forceinline__ int remap_row(int m) {
    int w = m / NWIN, n = m - w * NWIN;
    int b = w >> 6, widx = w & 63;
    int wi = widx >> 3, wj = widx & 7;
    int ti = n / WSZ, tj = n - ti * WSZ;
    int i0 = wi * WSZ + ti + SSH; if (i0 >= HH) i0 -= HH;
    int j0 = wj * WSZ + tj + SSH; if (j0 >= HH) j0 -= HH;
    return b * LL + i0 * HH + j0;
}

__device__ __forceinline__ uint32_t f2tf(float f) {
    uint32_t r; asm("cvt.rna.tf32.f32 %0, %1;" : "=r"(r) : "f"(f)); return r;
}

// ---------------- LayerNorm ----------------
template<bool GATHER>
__global__ void ln_kernel(const float* __restrict__ x, const float* __restrict__ g,
                          const float* __restrict__ b, float* __restrict__ y) {
    int m = blockIdx.x;
    int r = GATHER ? remap_row(m) : m;
    int tid = threadIdx.x;
    float val = x[(size_t)r * CC + tid];
    float s = val, s2 = val * val;
    #pragma unroll
    for (int off = 16; off; off >>= 1) {
        s  += __shfl_xor_sync(~0u, s,  off);
        s2 += __shfl_xor_sync(~0u, s2, off);
    }
    __shared__ float red[12];
    int warp = tid >> 5, lane = tid & 31;
    if (lane == 0) { red[warp] = s; red[6 + warp] = s2; }
    __syncthreads();
    if (tid < 32) {
        float a = (tid < 6) ? red[tid]     : 0.f;
        float c = (tid < 6) ? red[6 + tid] : 0.f;
        #pragma unroll
        for (int off = 4; off; off >>= 1) {
            a += __shfl_xor_sync(~0u, a, off);
            c += __shfl_xor_sync(~0u, c, off);
        }
        if (tid == 0) { red[0] = a; red[1] = c; }
    }
    __syncthreads();
    float mean = red[0] * (1.f / CC);
    float var  = red[1] * (1.f / CC) - mean * mean;
    float inv  = rsqrtf(var + 1e-5f);
    y[(size_t)m * CC + tid] = (val - mean) * inv * g[tid] + b[tid];
}

// ---------------- tf32 tensor-core GEMM ----------------
// C[M,N] = A[M,K] @ B[K,N] + bias, tile 128x64x32, 8 warps, warp tile 32x32.
// EPI: 0 qkv-scale, 1 proj(remap+resid), 2 gelu, 3 accumulate
#define GBM 128
#define GBN 64
#define GBK 32
#define LDA 132
#define LDB 68

__device__ __forceinline__ void mma_tf32(float* d, const uint32_t* a, const uint32_t* b) {
    asm volatile(
        "mma.sync.aligned.m16n8k8.row.col.f32.tf32.tf32.f32 "
        "{%0,%1,%2,%3}, {%4,%5,%6,%7}, {%8,%9}, {%0,%1,%2,%3};"
        : "+f"(d[0]), "+f"(d[1]), "+f"(d[2]), "+f"(d[3])
        : "r"(a[0]), "r"(a[1]), "r"(a[2]), "r"(a[3]), "r"(b[0]), "r"(b[1]));
}

template<int EPI>
__global__ __launch_bounds__(256) void gemm_tc(
    const float* __restrict__ A, const float* __restrict__ B,
    const float* __restrict__ bias, float* __restrict__ C,
    int M, int N, int K, const float* __restrict__ resid)
{
    __shared__ uint32_t As[GBK][LDA];   // [k][m]
    __shared__ uint32_t Bs[GBK][LDB];   // [k][n]

    int bm = blockIdx.y * GBM;
    int bn = blockIdx.x * GBN;
    int tid = threadIdx.x;
    int lane = tid & 31;
    int lp = lane >> 2, lq = lane & 3;
    int warp = tid >> 5;
    int wm = warp & 3;        // 4 warps along M
    int wn = warp >> 2;       // 2 warps along N
    int m0 = wm * 32, n0 = wn * 32;

    float acc[2][4][4] = {};

    int arow = tid >> 3;            // 0..31 (plus p*32)
    int acol = (tid & 7) << 2;      // 0,4,..,28
    int brow = tid >> 4;            // 0..15 (plus p*16)
    int bcol = (tid & 15) << 2;     // 0..60

    for (int k0 = 0; k0 < K; k0 += GBK) {
        float4 aR[4], bR[2];
        #pragma unroll
        for (int p = 0; p < 4; p++)
            aR[p] = *(const float4*)&A[(size_t)(bm + p * 32 + arow) * K + k0 + acol];
        #pragma unroll
        for (int p = 0; p < 2; p++)
            bR[p] = *(const float4*)&B[(size_t)(k0 + p * 16 + brow) * N + bn + bcol];

        __syncthreads();
        #pragma unroll
        for (int p = 0; p < 4; p++) {
            As[acol + 0][p * 32 + arow] = f2tf(aR[p].x);
            As[acol + 1][p * 32 + arow] = f2tf(aR[p].y);
            As[acol + 2][p * 32 + arow] = f2tf(aR[p].z);
            As[acol + 3][p * 32 + arow] = f2tf(aR[p].w);
        }
        #pragma unroll
        for (int p = 0; p < 2; p++) {
            Bs[p * 16 + brow][bcol + 0] = f2tf(bR[p].x);
            Bs[p * 16 + brow][bcol + 1] = f2tf(bR[p].y);
            Bs[p * 16 + brow][bcol + 2] = f2tf(bR[p].z);
            Bs[p * 16 + brow][bcol + 3] = f2tf(bR[p].w);
        }
        __syncthreads();

        #pragma unroll
        for (int ks = 0; ks < 4; ks++) {
            int kb = ks * 8;
            uint32_t af[2][4], bf[4][2];
            #pragma unroll
            for (int mt = 0; mt < 2; mt++) {
                int mr = m0 + mt * 16 + lp;
                af[mt][0] = As[kb + lq    ][mr    ];
                af[mt][1] = As[kb + lq    ][mr + 8];
                af[mt][2] = As[kb + lq + 4][mr    ];
                af[mt][3] = As[kb + lq + 4][mr + 8];
            }
            #pragma unroll
            for (int nt = 0; nt < 4; nt++) {
                int nc = n0 + nt * 8 + lp;
                bf[nt][0] = Bs[kb + lq    ][nc];
                bf[nt][1] = Bs[kb + lq + 4][nc];
            }
            #pragma unroll
            for (int mt = 0; mt < 2; mt++)
                #pragma unroll
                for (int nt = 0; nt < 4; nt++)
                    mma_tf32(acc[mt][nt], af[mt], bf[nt]);
        }
    }

    // epilogue: thread holds rows (m0+mt*16+lp, +8), cols (n0+nt*8+2lq, +1)
    #pragma unroll
    for (int mt = 0; mt < 2; mt++) {
        #pragma unroll
        for (int half = 0; half < 2; half++) {
            int m = bm + m0 + mt * 16 + lp + half * 8;
            int row = (EPI == 1) ? remap_row(m) : m;
            #pragma unroll
            for (int nt = 0; nt < 4; nt++) {
                int n = bn + n0 + nt * 8 + 2 * lq;
                float v0 = acc[mt][nt][half * 2 + 0] + bias[n];
                float v1 = acc[mt][nt][half * 2 + 1] + bias[n + 1];
                if (EPI == 0) {
                    if (n < CC)     v0 *= QSCALE;
                    if (n + 1 < CC) v1 *= QSCALE;
                } else if (EPI == 1) {
                    const float2 rv = *(const float2*)&resid[(size_t)row * N + n];
                    v0 += rv.x; v1 += rv.y;
                } else if (EPI == 2) {
                    v0 = 0.5f * v0 * (1.f + erff(v0 * 0.70710678118654752f));
                    v1 = 0.5f * v1 * (1.f + erff(v1 * 0.70710678118654752f));
                } else if (EPI == 3) {
                    const float2 cv = *(const float2*)&C[(size_t)row * N + n];
                    v0 += cv.x; v1 += cv.y;
                }
                *(float2*)&C[(size_t)row * N + n] = make_float2(v0, v1);
            }
        }
    }
}

// ---------------- windowed attention ----------------
__global__ __launch_bounds__(256) void attn_kernel(
    const float* __restrict__ qkv, const float* __restrict__ rel_table,
    const int* __restrict__ rel_index, const float* __restrict__ mask,
    float* __restrict__ o)
{
    int w = blockIdx.x;
    int h = blockIdx.y;
    int widx = w & 63;
    int tid = threadIdx.x;

    __shared__ float q[NWIN][33], k[NWIN][33], v[NWIN][33];
    __shared__ float S[NWIN][NWIN];

    const float* base = qkv + (size_t)w * NWIN * (3 * CC) + h * HD;
    for (int e = tid; e < NWIN * HD; e += 256) {
        int i = e >> 5, d = e & 31;
        q[i][d] = base[i * (3 * CC) + d];
        k[i][d] = base[i * (3 * CC) + CC + d];
        v[i][d] = base[i * (3 * CC) + 2 * CC + d];
    }
    __syncthreads();

    for (int e = tid; e < NWIN * NWIN; e += 256) {
        int i = e / NWIN, j = e - i * NWIN;
        float s = 0.f;
        #pragma unroll
        for (int d = 0; d < HD; d++) s = fmaf(q[i][d], k[j][d], s);
        s += rel_table[rel_index[e] * NHD + h];
        s += mask[(size_t)widx * (NWIN * NWIN) + e];
        S[i][j] = s;
    }
    __syncthreads();

    int warp = tid >> 5, lane = tid & 31;
    for (int i = warp; i < NWIN; i += 8) {
        float a  = S[i][lane];
        float b2 = (lane + 32 < NWIN) ? S[i][lane + 32] : -1e30f;
        float mx = fmaxf(a, b2);
        #pragma unroll
        for (int off = 16; off; off >>= 1) mx = fmaxf(mx, __shfl_xor_sync(~0u, mx, off));
        float e1 = __expf(a - mx);
        float e2 = (lane + 32 < NWIN) ? __expf(b2 - mx) : 0.f;
        float sm = e1 + e2;
        #pragma unroll
        for (int off = 16; off; off >>= 1) sm += __shfl_xor_sync(~0u, sm, off);
        float inv = 1.f / sm;
        S[i][lane] = e1 * inv;
        if (lane + 32 < NWIN) S[i][lane + 32] = e2 * inv;
    }
    __syncthreads();

    float* orow = o + (size_t)w * NWIN * CC + h * HD;
    for (int e = tid; e < NWIN * HD; e += 256) {
        int i = e >> 5, d = e & 31;
        float s = 0.f;
        #pragma unroll
        for (int j = 0; j < NWIN; j++) s = fmaf(S[i][j], v[j][d], s);
        orow[i * CC + d] = s;
    }
}

// ---------------- launch ----------------
extern "C" void kernel_launch(void* const* d_in, const int* in_sizes, int n_in,
                              void* d_out, int out_size) {
    const float* x        = (const float*)d_in[0];
    const float* norm1_g  = (const float*)d_in[1];
    const float* norm1_b  = (const float*)d_in[2];
    const float* qkv_w    = (const float*)d_in[3];
    const float* qkv_b    = (const float*)d_in[4];
    const float* proj_w   = (const float*)d_in[5];
    const float* proj_b   = (const float*)d_in[6];
    const float* norm2_g  = (const float*)d_in[7];
    const float* norm2_b  = (const float*)d_in[8];
    const float* fc1_w    = (const float*)d_in[9];
    const float* fc1_b    = (const float*)d_in[10];
    const float* fc2_w    = (const float*)d_in[11];
    const float* fc2_b    = (const float*)d_in[12];
    const float* rel_table= (const float*)d_in[13];
    const int*   rel_index= (const int*)  d_in[14];
    const float* mask     = (const float*)d_in[15];
    float* out = (float*)d_out;

    float *xw, *qkv, *o, *h1;
    cudaGetSymbolAddress((void**)&xw,  g_xw);
    cudaGetSymbolAddress((void**)&qkv, g_qkv);
    cudaGetSymbolAddress((void**)&o,   g_o);
    cudaGetSymbolAddress((void**)&h1,  g_h1);

    ln_kernel<true><<<MROWS, CC>>>(x, norm1_g, norm1_b, xw);
    gemm_tc<0><<<dim3((3*CC)/GBN, MROWS/GBM), 256>>>(xw, qkv_w, qkv_b, qkv,
                                                     MROWS, 3*CC, CC, nullptr);
    attn_kernel<<<dim3(BW, NHD), 256>>>(qkv, rel_table, rel_index, mask, o);
    gemm_tc<1><<<dim3(CC/GBN, MROWS/GBM), 256>>>(o, proj_w, proj_b, out,
                                                 MROWS, CC, CC, x);
    ln_kernel<false><<<MROWS, CC>>>(out, norm2_g, norm2_b, xw);
    gemm_tc<2><<<dim3(HID/GBN, MROWS/GBM), 256>>>(xw, fc1_w, fc1_b, h1,
                                                  MROWS, HID, CC, nullptr);
    gemm_tc<3><<<dim3(CC/GBN, MROWS/GBM), 256>>>(h1, fc2_w, fc2_b, out,
                                                 MROWS, CC, HID, nullptr);
}

// round 3
// speedup vs baseline: 1.9443x; 1.1640x over previous
#include <cuda_runtime.h>
#include <cuda_bf16.h>
#include <cstdint>

// ---------------- problem constants ----------------
#define BB   32
#define HH   56
#define CC   192
#define LL   (HH*HH)
#define NHD  6
#define HD   32
#define WSZ  7
#define SSH  3
#define NWIN 49
#define BW   2048
#define MROWS (BW*NWIN)        // 100352
#define HID  768
#define QSCALE 0.17677669529663687f

// ---------------- scratch ----------------
__device__ float g_xw [(size_t)MROWS*CC];
__device__ float g_qkv[(size_t)MROWS*3*CC];
__device__ float g_o  [(size_t)MROWS*CC];
__device__ float g_h1 [(size_t)MROWS*HID];

__device__ __forceinline__ int remap_row(int m) {
    int w = m / NWIN, n = m - w * NWIN;
    int b = w >> 6, widx = w & 63;
    int wi = widx >> 3, wj = widx & 7;
    int ti = n / WSZ, tj = n - ti * WSZ;
    int i0 = wi * WSZ + ti + SSH; if (i0 >= HH) i0 -= HH;
    int j0 = wj * WSZ + tj + SSH; if (j0 >= HH) j0 -= HH;
    return b * LL + i0 * HH + j0;
}

__device__ __forceinline__ uint32_t f2tf(float f) {
    uint32_t r; asm("cvt.rna.tf32.f32 %0, %1;" : "=r"(r) : "f"(f)); return r;
}

// ---------------- LayerNorm ----------------
template<bool GATHER>
__global__ void ln_kernel(const float* __restrict__ x, const float* __restrict__ g,
                          const float* __restrict__ b, float* __restrict__ y) {
    int m = blockIdx.x;
    int r = GATHER ? remap_row(m) : m;
    int tid = threadIdx.x;
    float val = x[(size_t)r * CC + tid];
    float s = val, s2 = val * val;
    #pragma unroll
    for (int off = 16; off; off >>= 1) {
        s  += __shfl_xor_sync(~0u, s,  off);
        s2 += __shfl_xor_sync(~0u, s2, off);
    }
    __shared__ float red[12];
    int warp = tid >> 5, lane = tid & 31;
    if (lane == 0) { red[warp] = s; red[6 + warp] = s2; }
    __syncthreads();
    if (tid < 32) {
        float a = (tid < 6) ? red[tid]     : 0.f;
        float c = (tid < 6) ? red[6 + tid] : 0.f;
        #pragma unroll
        for (int off = 4; off; off >>= 1) {
            a += __shfl_xor_sync(~0u, a, off);
            c += __shfl_xor_sync(~0u, c, off);
        }
        if (tid == 0) { red[0] = a; red[1] = c; }
    }
    __syncthreads();
    float mean = red[0] * (1.f / CC);
    float var  = red[1] * (1.f / CC) - mean * mean;
    float inv  = rsqrtf(var + 1e-5f);
    y[(size_t)m * CC + tid] = (val - mean) * inv * g[tid] + b[tid];
}

// ---------------- tf32 tensor-core GEMM, fragment-order smem --------------
// C[M,N] = A[M,K] @ B[K,N] + bias, tile 128x64x32, 8 warps (4M x 2N), warp 32x32.
#define GBM 128
#define GBN 64
#define GBK 32
// A frag tiles: 8 (tm) x 4 (tk), each 32 lanes x 4 vals; padded stride 132 words
#define APAD 132
// B frag tiles: 4 (tk) x 8 (tn), each 32 lanes x 2 vals; padded stride 66 words
#define BPAD 66

__device__ __forceinline__ void mma_tf32(float* d, uint32_t a0, uint32_t a1,
                                         uint32_t a2, uint32_t a3,
                                         uint32_t b0, uint32_t b1) {
    asm volatile(
        "mma.sync.aligned.m16n8k8.row.col.f32.tf32.tf32.f32 "
        "{%0,%1,%2,%3}, {%4,%5,%6,%7}, {%8,%9}, {%0,%1,%2,%3};"
        : "+f"(d[0]), "+f"(d[1]), "+f"(d[2]), "+f"(d[3])
        : "r"(a0), "r"(a1), "r"(a2), "r"(a3), "r"(b0), "r"(b1));
}

template<int EPI>
__global__ __launch_bounds__(256) void gemm_tc(
    const float* __restrict__ A, const float* __restrict__ B,
    const float* __restrict__ bias, float* __restrict__ C,
    int M, int N, int K, const float* __restrict__ resid)
{
    __shared__ __align__(16) uint32_t As[32 * APAD];   // 8 tm x 4 tk tiles
    __shared__ __align__(16) uint32_t Bs[32 * BPAD];   // 4 tk x 8 tn tiles

    int bm = blockIdx.y * GBM;
    int bn = blockIdx.x * GBN;
    int tid = threadIdx.x;
    int lane = tid & 31;
    int lp = lane >> 2, lq = lane & 3;
    int warp = tid >> 5;
    int wm = warp & 3;        // 4 warps along M (32 rows each)
    int wn = warp >> 2;       // 2 warps along N (32 cols each)

    float acc[2][4][4] = {};

    // gmem load assignments
    int arow = tid >> 3;            // 0..31 (+ p*32)
    int acol = (tid & 7) << 2;      // 0,4,...,28
    int brow = tid >> 4;            // 0..15 (+ p*16)
    int bcol = (tid & 15) << 2;     // 0..60

    // A writer constants: element (r, c=acol+i)
    int atk = acol >> 3;            // k-tile of this thread's A columns
    int asel_hi = (acol >> 2) & 1;  // hi half of k within tile
    // B writer: tn/lane derived per element below

    for (int k0 = 0; k0 < K; k0 += GBK) {
        float4 aR[4], bR[2];
        #pragma unroll
        for (int p = 0; p < 4; p++)
            aR[p] = *(const float4*)&A[(size_t)(bm + p * 32 + arow) * K + k0 + acol];
        #pragma unroll
        for (int p = 0; p < 2; p++)
            bR[p] = *(const float4*)&B[(size_t)(k0 + p * 16 + brow) * N + bn + bcol];

        __syncthreads();
        // scatter A into fragment order: As[(tm*4+tk)*APAD + lane*4 + j]
        #pragma unroll
        for (int p = 0; p < 4; p++) {
            int r  = p * 32 + arow;
            int tm = r >> 4;
            int rm = r & 15;
            int sel = rm >> 3;            // +8 row half -> j bit0
            int lpa = rm & 7;
            int base = (tm * 4 + atk) * APAD + (asel_hi * 2 + sel);
            float va[4] = {aR[p].x, aR[p].y, aR[p].z, aR[p].w};
            #pragma unroll
            for (int i = 0; i < 4; i++)
                As[base + (lpa * 4 + i) * 4] = f2tf(va[i]);
        }
        // scatter B into fragment order: Bs[(tk*8+tn)*BPAD + lane*2 + hi]
        #pragma unroll
        for (int p = 0; p < 2; p++) {
            int kk  = p * 16 + brow;
            int tk  = kk >> 3;
            int kq  = kk & 7;
            int bhi = kq >> 2;
            int blq = kq & 3;
            int tn  = bcol >> 3;
            int lpb0 = bcol & 7;
            int base = (tk * 8 + tn) * BPAD + bhi;
            float vb[4] = {bR[p].x, bR[p].y, bR[p].z, bR[p].w};
            #pragma unroll
            for (int i = 0; i < 4; i++)
                Bs[base + ((lpb0 + i) * 4 + blq) * 2] = f2tf(vb[i]);
        }
        __syncthreads();

        #pragma unroll
        for (int ks = 0; ks < 4; ks++) {
            uint4 af[2];
            uint2 bf[4];
            #pragma unroll
            for (int mt = 0; mt < 2; mt++)
                af[mt] = *(const uint4*)&As[((wm * 2 + mt) * 4 + ks) * APAD + lane * 4];
            #pragma unroll
            for (int nt = 0; nt < 4; nt++)
                bf[nt] = *(const uint2*)&Bs[(ks * 8 + wn * 4 + nt) * BPAD + lane * 2];
            #pragma unroll
            for (int mt = 0; mt < 2; mt++)
                #pragma unroll
                for (int nt = 0; nt < 4; nt++)
                    mma_tf32(acc[mt][nt], af[mt].x, af[mt].y, af[mt].z, af[mt].w,
                             bf[nt].x, bf[nt].y);
        }
    }

    int m0 = wm * 32, n0 = wn * 32;
    #pragma unroll
    for (int mt = 0; mt < 2; mt++) {
        #pragma unroll
        for (int half = 0; half < 2; half++) {
            int m = bm + m0 + mt * 16 + lp + half * 8;
            int row = (EPI == 1) ? remap_row(m) : m;
            #pragma unroll
            for (int nt = 0; nt < 4; nt++) {
                int n = bn + n0 + nt * 8 + 2 * lq;
                float v0 = acc[mt][nt][half * 2 + 0] + bias[n];
                float v1 = acc[mt][nt][half * 2 + 1] + bias[n + 1];
                if (EPI == 0) {
                    if (n < CC)     v0 *= QSCALE;
                    if (n + 1 < CC) v1 *= QSCALE;
                } else if (EPI == 1) {
                    const float2 rv = *(const float2*)&resid[(size_t)row * N + n];
                    v0 += rv.x; v1 += rv.y;
                } else if (EPI == 2) {
                    v0 = 0.5f * v0 * (1.f + erff(v0 * 0.70710678118654752f));
                    v1 = 0.5f * v1 * (1.f + erff(v1 * 0.70710678118654752f));
                } else if (EPI == 3) {
                    const float2 cv = *(const float2*)&C[(size_t)row * N + n];
                    v0 += cv.x; v1 += cv.y;
                }
                *(float2*)&C[(size_t)row * N + n] = make_float2(v0, v1);
            }
        }
    }
}

// ---------------- windowed attention ----------------
__global__ __launch_bounds__(256) void attn_kernel(
    const float* __restrict__ qkv, const float* __restrict__ rel_table,
    const int* __restrict__ rel_index, const float* __restrict__ mask,
    float* __restrict__ o)
{
    int w = blockIdx.x;
    int h = blockIdx.y;
    int widx = w & 63;
    int tid = threadIdx.x;

    __shared__ float q[NWIN][33], k[NWIN][33], v[NWIN][33];
    __shared__ float S[NWIN][NWIN];

    const float* base = qkv + (size_t)w * NWIN * (3 * CC) + h * HD;
    for (int e = tid; e < NWIN * HD; e += 256) {
        int i = e >> 5, d = e & 31;
        q[i][d] = base[i * (3 * CC) + d];
        k[i][d] = base[i * (3 * CC) + CC + d];
        v[i][d] = base[i * (3 * CC) + 2 * CC + d];
    }
    __syncthreads();

    for (int e = tid; e < NWIN * NWIN; e += 256) {
        int i = e / NWIN, j = e - i * NWIN;
        float s = 0.f;
        #pragma unroll
        for (int d = 0; d < HD; d++) s = fmaf(q[i][d], k[j][d], s);
        s += rel_table[rel_index[e] * NHD + h];
        s += mask[(size_t)widx * (NWIN * NWIN) + e];
        S[i][j] = s;
    }
    __syncthreads();

    int warp = tid >> 5, lane = tid & 31;
    for (int i = warp; i < NWIN; i += 8) {
        float a  = S[i][lane];
        float b2 = (lane + 32 < NWIN) ? S[i][lane + 32] : -1e30f;
        float mx = fmaxf(a, b2);
        #pragma unroll
        for (int off = 16; off; off >>= 1) mx = fmaxf(mx, __shfl_xor_sync(~0u, mx, off));
        float e1 = __expf(a - mx);
        float e2 = (lane + 32 < NWIN) ? __expf(b2 - mx) : 0.f;
        float sm = e1 + e2;
        #pragma unroll
        for (int off = 16; off; off >>= 1) sm += __shfl_xor_sync(~0u, sm, off);
        float inv = 1.f / sm;
        S[i][lane] = e1 * inv;
        if (lane + 32 < NWIN) S[i][lane + 32] = e2 * inv;
    }
    __syncthreads();

    float* orow = o + (size_t)w * NWIN * CC + h * HD;
    for (int e = tid; e < NWIN * HD; e += 256) {
        int i = e >> 5, d = e & 31;
        float s = 0.f;
        #pragma unroll
        for (int j = 0; j < NWIN; j++) s = fmaf(S[i][j], v[j][d], s);
        orow[i * CC + d] = s;
    }
}

// ---------------- launch ----------------
extern "C" void kernel_launch(void* const* d_in, const int* in_sizes, int n_in,
                              void* d_out, int out_size) {
    const float* x        = (const float*)d_in[0];
    const float* norm1_g  = (const float*)d_in[1];
    const float* norm1_b  = (const float*)d_in[2];
    const float* qkv_w    = (const float*)d_in[3];
    const float* qkv_b    = (const float*)d_in[4];
    const float* proj_w   = (const float*)d_in[5];
    const float* proj_b   = (const float*)d_in[6];
    const float* norm2_g  = (const float*)d_in[7];
    const float* norm2_b  = (const float*)d_in[8];
    const float* fc1_w    = (const float*)d_in[9];
    const float* fc1_b    = (const float*)d_in[10];
    const float* fc2_w    = (const float*)d_in[11];
    const float* fc2_b    = (const float*)d_in[12];
    const float* rel_table= (const float*)d_in[13];
    const int*   rel_index= (const int*)  d_in[14];
    const float* mask     = (const float*)d_in[15];
    float* out = (float*)d_out;

    float *xw, *qkv, *o, *h1;
    cudaGetSymbolAddress((void**)&xw,  g_xw);
    cudaGetSymbolAddress((void**)&qkv, g_qkv);
    cudaGetSymbolAddress((void**)&o,   g_o);
    cudaGetSymbolAddress((void**)&h1,  g_h1);

    ln_kernel<true><<<MROWS, CC>>>(x, norm1_g, norm1_b, xw);
    gemm_tc<0><<<dim3((3*CC)/GBN, MROWS/GBM), 256>>>(xw, qkv_w, qkv_b, qkv,
                                                     MROWS, 3*CC, CC, nullptr);
    attn_kernel<<<dim3(BW, NHD), 256>>>(qkv, rel_table, rel_index, mask, o);
    gemm_tc<1><<<dim3(CC/GBN, MROWS/GBM), 256>>>(o, proj_w, proj_b, out,
                                                 MROWS, CC, CC, x);
    ln_kernel<false><<<MROWS, CC>>>(out, norm2_g, norm2_b, xw);
    gemm_tc<2><<<dim3(HID/GBN, MROWS/GBM), 256>>>(xw, fc1_w, fc1_b, h1,
                                                  MROWS, HID, CC, nullptr);
    gemm_tc<3><<<dim3(CC/GBN, MROWS/GBM), 256>>>(h1, fc2_w, fc2_b, out,
                                                 MROWS, CC, HID, nullptr);
}

// round 4
// speedup vs baseline: 2.3446x; 1.2059x over previous
#include <cuda_runtime.h>
#include <cuda_bf16.h>
#include <cstdint>

// ---------------- problem constants ----------------
#define BB   32
#define HH   56
#define CC   192
#define LL   (HH*HH)
#define NHD  6
#define HD   32
#define WSZ  7
#define SSH  3
#define NWIN 49
#define BW   2048
#define MROWS (BW*NWIN)        // 100352
#define HID  768
#define QSCALE 0.17677669529663687f

// ---------------- scratch ----------------
__device__ float g_xw [(size_t)MROWS*CC];
__device__ float g_qkv[(size_t)MROWS*3*CC];
__device__ float g_o  [(size_t)MROWS*CC];
__device__ float g_h1 [(size_t)MROWS*HID];

__device__ __forceinline__ int remap_row(int m) {
    int w = m / NWIN, n = m - w * NWIN;
    int b = w >> 6, widx = w & 63;
    int wi = widx >> 3, wj = widx & 7;
    int ti = n / WSZ, tj = n - ti * WSZ;
    int i0 = wi * WSZ + ti + SSH; if (i0 >= HH) i0 -= HH;
    int j0 = wj * WSZ + tj + SSH; if (j0 >= HH) j0 -= HH;
    return b * LL + i0 * HH + j0;
}

__device__ __forceinline__ uint32_t pack_bf2(float lo, float hi) {
    __nv_bfloat162 t = __floats2bfloat162_rn(lo, hi);
    return *reinterpret_cast<uint32_t*>(&t);
}

// ---------------- LayerNorm ----------------
template<bool GATHER>
__global__ void ln_kernel(const float* __restrict__ x, const float* __restrict__ g,
                          const float* __restrict__ b, float* __restrict__ y) {
    int m = blockIdx.x;
    int r = GATHER ? remap_row(m) : m;
    int tid = threadIdx.x;
    float val = x[(size_t)r * CC + tid];
    float s = val, s2 = val * val;
    #pragma unroll
    for (int off = 16; off; off >>= 1) {
        s  += __shfl_xor_sync(~0u, s,  off);
        s2 += __shfl_xor_sync(~0u, s2, off);
    }
    __shared__ float red[12];
    int warp = tid >> 5, lane = tid & 31;
    if (lane == 0) { red[warp] = s; red[6 + warp] = s2; }
    __syncthreads();
    if (tid < 32) {
        float a = (tid < 6) ? red[tid]     : 0.f;
        float c = (tid < 6) ? red[6 + tid] : 0.f;
        #pragma unroll
        for (int off = 4; off; off >>= 1) {
            a += __shfl_xor_sync(~0u, a, off);
            c += __shfl_xor_sync(~0u, c, off);
        }
        if (tid == 0) { red[0] = a; red[1] = c; }
    }
    __syncthreads();
    float mean = red[0] * (1.f / CC);
    float var  = red[1] * (1.f / CC) - mean * mean;
    float inv  = rsqrtf(var + 1e-5f);
    y[(size_t)m * CC + tid] = (val - mean) * inv * g[tid] + b[tid];
}

// ---------------- bf16 tensor-core GEMM, fragment-order smem, dbl-buffer --
// C[M,N] = A[M,K] @ B[K,N] + bias. Tile 128x64x32, 8 warps (4M x 2N), warp 32x32.
// mma.m16n8k16.bf16 : A-frag 4 x b32, B-frag 2 x b32, per k-tile(32) 2 k-steps.
#define GBM 128
#define GBN 64
#define GBK 32
#define ATS 132     // A frag-tile stride (128 u32 + 4 pad); 16 tiles (8 tm x 2 tk)
#define BTS 66      // B frag-tile stride (64 u32 + 2 pad); 16 tiles (2 tk x 8 tn)
#define ASZ (16*ATS)
#define BSZ (16*BTS)

__device__ __forceinline__ void mma_bf16(float* d, uint32_t a0, uint32_t a1,
                                         uint32_t a2, uint32_t a3,
                                         uint32_t b0, uint32_t b1) {
    asm volatile(
        "mma.sync.aligned.m16n8k16.row.col.f32.bf16.bf16.f32 "
        "{%0,%1,%2,%3}, {%4,%5,%6,%7}, {%8,%9}, {%0,%1,%2,%3};"
        : "+f"(d[0]), "+f"(d[1]), "+f"(d[2]), "+f"(d[3])
        : "r"(a0), "r"(a1), "r"(a2), "r"(a3), "r"(b0), "r"(b1));
}

template<int EPI>
__global__ __launch_bounds__(256) void gemm_tc(
    const float* __restrict__ A, const float* __restrict__ B,
    const float* __restrict__ bias, float* __restrict__ C,
    int M, int N, int K, const float* __restrict__ resid)
{
    __shared__ __align__(16) uint32_t As[2][ASZ];
    __shared__ __align__(16) uint32_t Bs[2][BSZ];

    int bm = blockIdx.y * GBM;
    int bn = blockIdx.x * GBN;
    int tid = threadIdx.x;
    int lane = tid & 31;
    int lp = lane >> 2, lq = lane & 3;
    int warp = tid >> 5;
    int wm = warp & 3;
    int wn = warp >> 2;

    float acc[2][4][4] = {};

    // A gmem: 4 float4 per thread, rows arow+p*32, cols acol..acol+3
    int arow = tid >> 3;                 // 0..31
    int acol = (tid & 7) << 2;           // 0,4,...,28
    // B gmem: 2 float4 per thread, rows kk0/kk0+1, cols bcol..bcol+3
    int kk0  = (tid >> 4) << 1;          // 0,2,...,30
    int bcol = (tid & 15) << 2;          // 0..60

    // A writer constants
    int a_tk = acol >> 4;                // 0/1
    int a_kc = acol & 15;                // 0,4,8,12
    int a_jk = (a_kc >> 3) << 1;         // 0 or 2 (k-half -> reg j high bit)
    int a_lq = (a_kc & 7) >> 1;          // 0 or 2
    // B writer constants
    int b_tk = kk0 >> 4;
    int b_kq = kk0 & 15;
    int b_lq = (b_kq >> 1) & 3;
    int b_j  = b_kq >> 3;

    float4 aR[4], bR0, bR1;
    const int nk = K >> 5;

    auto load_g = [&](int k0) {
        #pragma unroll
        for (int p = 0; p < 4; p++)
            aR[p] = *(const float4*)&A[(size_t)(bm + p * 32 + arow) * K + k0 + acol];
        bR0 = *(const float4*)&B[(size_t)(k0 + kk0    ) * N + bn + bcol];
        bR1 = *(const float4*)&B[(size_t)(k0 + kk0 + 1) * N + bn + bcol];
    };

    auto store_s = [&](int buf) {
        #pragma unroll
        for (int p = 0; p < 4; p++) {
            int r  = p * 32 + arow;
            int tm = r >> 4;
            int rm = r & 15;
            int j  = (rm >> 3) + a_jk;
            int lf = (rm & 7) * 4 + a_lq;       // fragment lane base
            int base = (tm * 2 + a_tk) * ATS + j;
            As[buf][base + (lf    ) * 4] = pack_bf2(aR[p].x, aR[p].y);
            As[buf][base + (lf + 1) * 4] = pack_bf2(aR[p].z, aR[p].w);
        }
        float b0v[4] = {bR0.x, bR0.y, bR0.z, bR0.w};
        float b1v[4] = {bR1.x, bR1.y, bR1.z, bR1.w};
        #pragma unroll
        for (int i = 0; i < 4; i++) {
            int n  = bcol + i;
            int tn = n >> 3;
            int lf = (n & 7) * 4 + b_lq;
            Bs[buf][(b_tk * 8 + tn) * BTS + lf * 2 + b_j] = pack_bf2(b0v[i], b1v[i]);
        }
    };

    auto do_mma = [&](int buf) {
        #pragma unroll
        for (int ks = 0; ks < 2; ks++) {
            uint4 af[2];
            uint2 bf[4];
            #pragma unroll
            for (int mt = 0; mt < 2; mt++)
                af[mt] = *(const uint4*)&As[buf][((wm * 2 + mt) * 2 + ks) * ATS + lane * 4];
            #pragma unroll
            for (int nt = 0; nt < 4; nt++)
                bf[nt] = *(const uint2*)&Bs[buf][(ks * 8 + wn * 4 + nt) * BTS + lane * 2];
            #pragma unroll
            for (int mt = 0; mt < 2; mt++)
                #pragma unroll
                for (int nt = 0; nt < 4; nt++)
                    mma_bf16(acc[mt][nt], af[mt].x, af[mt].y, af[mt].z, af[mt].w,
                             bf[nt].x, bf[nt].y);
        }
    };

    load_g(0);
    store_s(0);
    __syncthreads();
    int cur = 0;
    for (int it = 1; it < nk; it++) {
        load_g(it << 5);
        do_mma(cur);
        __syncthreads();
        store_s(cur ^ 1);
        __syncthreads();
        cur ^= 1;
    }
    do_mma(cur);

    int m0 = wm * 32, n0 = wn * 32;
    #pragma unroll
    for (int mt = 0; mt < 2; mt++) {
        #pragma unroll
        for (int half = 0; half < 2; half++) {
            int m = bm + m0 + mt * 16 + lp + half * 8;
            int row = (EPI == 1) ? remap_row(m) : m;
            #pragma unroll
            for (int nt = 0; nt < 4; nt++) {
                int n = bn + n0 + nt * 8 + 2 * lq;
                float v0 = acc[mt][nt][half * 2 + 0] + bias[n];
                float v1 = acc[mt][nt][half * 2 + 1] + bias[n + 1];
                if (EPI == 0) {
                    if (n < CC)     v0 *= QSCALE;
                    if (n + 1 < CC) v1 *= QSCALE;
                } else if (EPI == 1) {
                    const float2 rv = *(const float2*)&resid[(size_t)row * N + n];
                    v0 += rv.x; v1 += rv.y;
                } else if (EPI == 2) {
                    v0 = 0.5f * v0 * (1.f + erff(v0 * 0.70710678118654752f));
                    v1 = 0.5f * v1 * (1.f + erff(v1 * 0.70710678118654752f));
                } else if (EPI == 3) {
                    const float2 cv = *(const float2*)&C[(size_t)row * N + n];
                    v0 += cv.x; v1 += cv.y;
                }
                *(float2*)&C[(size_t)row * N + n] = make_float2(v0, v1);
            }
        }
    }
}

// ---------------- windowed attention ----------------
__global__ __launch_bounds__(256) void attn_kernel(
    const float* __restrict__ qkv, const float* __restrict__ rel_table,
    const int* __restrict__ rel_index, const float* __restrict__ mask,
    float* __restrict__ o)
{
    int w = blockIdx.x;
    int h = blockIdx.y;
    int widx = w & 63;
    int tid = threadIdx.x;

    __shared__ float q[NWIN][33], k[NWIN][33], v[NWIN][33];
    __shared__ float S[NWIN][NWIN];

    const float* base = qkv + (size_t)w * NWIN * (3 * CC) + h * HD;
    for (int e = tid; e < NWIN * HD; e += 256) {
        int i = e >> 5, d = e & 31;
        q[i][d] = base[i * (3 * CC) + d];
        k[i][d] = base[i * (3 * CC) + CC + d];
        v[i][d] = base[i * (3 * CC) + 2 * CC + d];
    }
    __syncthreads();

    for (int e = tid; e < NWIN * NWIN; e += 256) {
        int i = e / NWIN, j = e - i * NWIN;
        float s = 0.f;
        #pragma unroll
        for (int d = 0; d < HD; d++) s = fmaf(q[i][d], k[j][d], s);
        s += rel_table[rel_index[e] * NHD + h];
        s += mask[(size_t)widx * (NWIN * NWIN) + e];
        S[i][j] = s;
    }
    __syncthreads();

    int warp = tid >> 5, lane = tid & 31;
    for (int i = warp; i < NWIN; i += 8) {
        float a  = S[i][lane];
        float b2 = (lane + 32 < NWIN) ? S[i][lane + 32] : -1e30f;
        float mx = fmaxf(a, b2);
        #pragma unroll
        for (int off = 16; off; off >>= 1) mx = fmaxf(mx, __shfl_xor_sync(~0u, mx, off));
        float e1 = __expf(a - mx);
        float e2 = (lane + 32 < NWIN) ? __expf(b2 - mx) : 0.f;
        float sm = e1 + e2;
        #pragma unroll
        for (int off = 16; off; off >>= 1) sm += __shfl_xor_sync(~0u, sm, off);
        float inv = 1.f / sm;
        S[i][lane] = e1 * inv;
        if (lane + 32 < NWIN) S[i][lane + 32] = e2 * inv;
    }
    __syncthreads();

    float* orow = o + (size_t)w * NWIN * CC + h * HD;
    for (int e = tid; e < NWIN * HD; e += 256) {
        int i = e >> 5, d = e & 31;
        float s = 0.f;
        #pragma unroll
        for (int j = 0; j < NWIN; j++) s = fmaf(S[i][j], v[j][d], s);
        orow[i * CC + d] = s;
    }
}

// ---------------- launch ----------------
extern "C" void kernel_launch(void* const* d_in, const int* in_sizes, int n_in,
                              void* d_out, int out_size) {
    const float* x        = (const float*)d_in[0];
    const float* norm1_g  = (const float*)d_in[1];
    const float* norm1_b  = (const float*)d_in[2];
    const float* qkv_w    = (const float*)d_in[3];
    const float* qkv_b    = (const float*)d_in[4];
    const float* proj_w   = (const float*)d_in[5];
    const float* proj_b   = (const float*)d_in[6];
    const float* norm2_g  = (const float*)d_in[7];
    const float* norm2_b  = (const float*)d_in[8];
    const float* fc1_w    = (const float*)d_in[9];
    const float* fc1_b    = (const float*)d_in[10];
    const float* fc2_w    = (const float*)d_in[11];
    const float* fc2_b    = (const float*)d_in[12];
    const float* rel_table= (const float*)d_in[13];
    const int*   rel_index= (const int*)  d_in[14];
    const float* mask     = (const float*)d_in[15];
    float* out = (float*)d_out;

    float *xw, *qkv, *o, *h1;
    cudaGetSymbolAddress((void**)&xw,  g_xw);
    cudaGetSymbolAddress((void**)&qkv, g_qkv);
    cudaGetSymbolAddress((void**)&o,   g_o);
    cudaGetSymbolAddress((void**)&h1,  g_h1);

    ln_kernel<true><<<MROWS, CC>>>(x, norm1_g, norm1_b, xw);
    gemm_tc<0><<<dim3((3*CC)/GBN, MROWS/GBM), 256>>>(xw, qkv_w, qkv_b, qkv,
                                                     MROWS, 3*CC, CC, nullptr);
    attn_kernel<<<dim3(BW, NHD), 256>>>(qkv, rel_table, rel_index, mask, o);
    gemm_tc<1><<<dim3(CC/GBN, MROWS/GBM), 256>>>(o, proj_w, proj_b, out,
                                                 MROWS, CC, CC, x);
    ln_kernel<false><<<MROWS, CC>>>(out, norm2_g, norm2_b, xw);
    gemm_tc<2><<<dim3(HID/GBN, MROWS/GBM), 256>>>(xw, fc1_w, fc1_b, h1,
                                                  MROWS, HID, CC, nullptr);
    gemm_tc<3><<<dim3(CC/GBN, MROWS/GBM), 256>>>(h1, fc2_w, fc2_b, out,
                                                 MROWS, CC, HID, nullptr);
}

// round 5
// speedup vs baseline: 2.8961x; 1.2352x over previous
#include <cuda_runtime.h>
#include <cuda_bf16.h>
#include <cstdint>

// ---------------- problem constants ----------------
#define BB   32
#define HH   56
#define CC   192
#define LL   (HH*HH)
#define NHD  6
#define HD   32
#define WSZ  7
#define SSH  3
#define NWIN 49
#define BW   2048
#define MROWS (BW*NWIN)        // 100352
#define HID  768
#define QSCALE 0.17677669529663687f

// ---------------- scratch ----------------
__device__ __nv_bfloat16 g_xw [(size_t)MROWS*CC];
__device__ float         g_qkv[(size_t)MROWS*3*CC];
__device__ __nv_bfloat16 g_o  [(size_t)MROWS*CC];
__device__ __nv_bfloat16 g_h1 [(size_t)MROWS*HID];
__device__ __nv_bfloat16 g_wq [(size_t)CC*3*CC];
__device__ __nv_bfloat16 g_wp [(size_t)CC*CC];
__device__ __nv_bfloat16 g_w1 [(size_t)CC*HID];
__device__ __nv_bfloat16 g_w2 [(size_t)HID*CC];

__device__ __forceinline__ int remap_row(int m) {
    int w = m / NWIN, n = m - w * NWIN;
    int b = w >> 6, widx = w & 63;
    int wi = widx >> 3, wj = widx & 7;
    int ti = n / WSZ, tj = n - ti * WSZ;
    int i0 = wi * WSZ + ti + SSH; if (i0 >= HH) i0 -= HH;
    int j0 = wj * WSZ + tj + SSH; if (j0 >= HH) j0 -= HH;
    return b * LL + i0 * HH + j0;
}

// ---------------- weight f32 -> bf16 ----------------
__global__ void cvt_kernel(const float* __restrict__ s, __nv_bfloat16* __restrict__ d, int n) {
    int i = blockIdx.x * 256 + threadIdx.x;
    if (i < n) d[i] = __float2bfloat16(s[i]);
}

// ---------------- LayerNorm (writes bf16) ----------------
template<bool GATHER>
__global__ void ln_kernel(const float* __restrict__ x, const float* __restrict__ g,
                          const float* __restrict__ b, __nv_bfloat16* __restrict__ y) {
    int m = blockIdx.x;
    int r = GATHER ? remap_row(m) : m;
    int tid = threadIdx.x;
    float val = x[(size_t)r * CC + tid];
    float s = val, s2 = val * val;
    #pragma unroll
    for (int off = 16; off; off >>= 1) {
        s  += __shfl_xor_sync(~0u, s,  off);
        s2 += __shfl_xor_sync(~0u, s2, off);
    }
    __shared__ float red[12];
    int warp = tid >> 5, lane = tid & 31;
    if (lane == 0) { red[warp] = s; red[6 + warp] = s2; }
    __syncthreads();
    if (tid < 32) {
        float a = (tid < 6) ? red[tid]     : 0.f;
        float c = (tid < 6) ? red[6 + tid] : 0.f;
        #pragma unroll
        for (int off = 4; off; off >>= 1) {
            a += __shfl_xor_sync(~0u, a, off);
            c += __shfl_xor_sync(~0u, c, off);
        }
        if (tid == 0) { red[0] = a; red[1] = c; }
    }
    __syncthreads();
    float mean = red[0] * (1.f / CC);
    float var  = red[1] * (1.f / CC) - mean * mean;
    float inv  = rsqrtf(var + 1e-5f);
    y[(size_t)m * CC + tid] = __float2bfloat16((val - mean) * inv * g[tid] + b[tid]);
}

// ---------------- bf16 GEMM: cp.async + ldmatrix + 3-stage pipeline ------
// C[M,N] = A[M,K]@B[K,N] + bias. Block 128x64x32, 8 warps (4Mx2N), warp 32x32.
#define GBM 128
#define GBN 64
#define AST 40                 // A smem row stride (bf16 elts): 80B -> conflict-free LDSM
#define BST 72                 // B smem row stride: 144B -> conflict-free LDSM
#define STG_ELTS (128*AST + 32*BST)   // 7424 bf16 per stage
#define NSTG 3

__device__ __forceinline__ void cp16(uint32_t saddr, const void* g) {
    asm volatile("cp.async.cg.shared.global [%0], [%1], 16;" :: "r"(saddr), "l"(g));
}
#define CP_COMMIT() asm volatile("cp.async.commit_group;")
#define CP_WAIT1()  asm volatile("cp.async.wait_group 1;")

__device__ __forceinline__ void ldsm_x4(uint32_t& r0, uint32_t& r1, uint32_t& r2,
                                        uint32_t& r3, uint32_t a) {
    asm volatile("ldmatrix.sync.aligned.m8n8.x4.shared.b16 {%0,%1,%2,%3}, [%4];"
                 : "=r"(r0), "=r"(r1), "=r"(r2), "=r"(r3) : "r"(a));
}
__device__ __forceinline__ void ldsm_x4t(uint32_t& r0, uint32_t& r1, uint32_t& r2,
                                         uint32_t& r3, uint32_t a) {
    asm volatile("ldmatrix.sync.aligned.m8n8.x4.trans.shared.b16 {%0,%1,%2,%3}, [%4];"
                 : "=r"(r0), "=r"(r1), "=r"(r2), "=r"(r3) : "r"(a));
}
__device__ __forceinline__ void mma_bf16(float* d, uint32_t a0, uint32_t a1,
                                         uint32_t a2, uint32_t a3,
                                         uint32_t b0, uint32_t b1) {
    asm volatile(
        "mma.sync.aligned.m16n8k16.row.col.f32.bf16.bf16.f32 "
        "{%0,%1,%2,%3}, {%4,%5,%6,%7}, {%8,%9}, {%0,%1,%2,%3};"
        : "+f"(d[0]), "+f"(d[1]), "+f"(d[2]), "+f"(d[3])
        : "r"(a0), "r"(a1), "r"(a2), "r"(a3), "r"(b0), "r"(b1));
}

template<int EPI, typename TOut>
__global__ __launch_bounds__(256) void gemm_tc(
    const __nv_bfloat16* __restrict__ A, const __nv_bfloat16* __restrict__ B,
    const float* __restrict__ bias, TOut* __restrict__ C,
    int M, int N, int K, const float* __restrict__ resid)
{
    __shared__ __align__(16) __nv_bfloat16 sm[NSTG * STG_ELTS];
    uint32_t sbase = (uint32_t)__cvta_generic_to_shared(sm);

    int bm = blockIdx.y * GBM, bn = blockIdx.x * GBN;
    int tid = threadIdx.x, lane = tid & 31;
    int lp = lane >> 2, lq = lane & 3;
    int warp = tid >> 5, wm = warp & 3, wn = warp >> 2;

    // cp.async assignments
    int a_r0 = tid >> 2;            // rows a_r0 and a_r0+64
    int a_c  = (tid & 3) * 8;       // 0,8,16,24
    int b_r  = tid >> 3;            // 0..31
    int b_c  = (tid & 7) * 8;       // 0..56

    // ldmatrix lane offsets
    int lrow = (lane & 7) + ((lane >> 3) & 1) * 8;
    int lcol = (lane >> 4) * 8;

    const int nk = K >> 5;
    float acc[2][4][4] = {};

    auto issue = [&](int it) {
        int s = it - (it / NSTG) * NSTG;
        uint32_t sa = sbase + (uint32_t)(s * STG_ELTS) * 2;
        int k0 = it << 5;
        cp16(sa + (uint32_t)(a_r0 * AST + a_c) * 2,
             A + (size_t)(bm + a_r0) * K + k0 + a_c);
        cp16(sa + (uint32_t)((a_r0 + 64) * AST + a_c) * 2,
             A + (size_t)(bm + a_r0 + 64) * K + k0 + a_c);
        cp16(sa + (uint32_t)(128 * AST + b_r * BST + b_c) * 2,
             B + (size_t)(k0 + b_r) * N + bn + b_c);
    };

    auto domma = [&](int it) {
        int s = it - (it / NSTG) * NSTG;
        uint32_t sa = sbase + (uint32_t)(s * STG_ELTS) * 2;
        uint32_t sb = sa + 128 * AST * 2;
        #pragma unroll
        for (int ks = 0; ks < 2; ks++) {
            uint32_t af[2][4], bfr[2][4];
            #pragma unroll
            for (int mt = 0; mt < 2; mt++)
                ldsm_x4(af[mt][0], af[mt][1], af[mt][2], af[mt][3],
                        sa + (uint32_t)((wm * 32 + mt * 16 + lrow) * AST + ks * 16 + lcol) * 2);
            #pragma unroll
            for (int g = 0; g < 2; g++)
                ldsm_x4t(bfr[g][0], bfr[g][1], bfr[g][2], bfr[g][3],
                         sb + (uint32_t)((ks * 16 + lrow) * BST + wn * 32 + g * 16 + lcol) * 2);
            #pragma unroll
            for (int mt = 0; mt < 2; mt++)
                #pragma unroll
                for (int nt = 0; nt < 4; nt++) {
                    int g = nt >> 1, h = nt & 1;
                    mma_bf16(acc[mt][nt], af[mt][0], af[mt][1], af[mt][2], af[mt][3],
                             bfr[g][h * 2], bfr[g][h * 2 + 1]);
                }
        }
    };

    issue(0); CP_COMMIT();
    issue(1); CP_COMMIT();
    for (int it = 0; it < nk; it++) {
        CP_WAIT1();
        __syncthreads();
        if (it + 2 < nk) issue(it + 2);
        CP_COMMIT();
        domma(it);
    }

    int m0 = wm * 32, n0 = wn * 32;
    #pragma unroll
    for (int mt = 0; mt < 2; mt++) {
        #pragma unroll
        for (int half = 0; half < 2; half++) {
            int m = bm + m0 + mt * 16 + lp + half * 8;
            int row = (EPI == 1) ? remap_row(m) : m;
            #pragma unroll
            for (int nt = 0; nt < 4; nt++) {
                int n = bn + n0 + nt * 8 + 2 * lq;
                float v0 = acc[mt][nt][half * 2 + 0] + bias[n];
                float v1 = acc[mt][nt][half * 2 + 1] + bias[n + 1];
                if constexpr (EPI == 0) {
                    if (n < CC)     v0 *= QSCALE;
                    if (n + 1 < CC) v1 *= QSCALE;
                    *(float2*)&((float*)C)[(size_t)row * N + n] = make_float2(v0, v1);
                } else if constexpr (EPI == 1) {
                    const float2 rv = *(const float2*)&resid[(size_t)row * N + n];
                    *(float2*)&((float*)C)[(size_t)row * N + n] =
                        make_float2(v0 + rv.x, v1 + rv.y);
                } else if constexpr (EPI == 2) {
                    v0 = 0.5f * v0 * (1.f + erff(v0 * 0.70710678118654752f));
                    v1 = 0.5f * v1 * (1.f + erff(v1 * 0.70710678118654752f));
                    *(__nv_bfloat162*)&((__nv_bfloat16*)C)[(size_t)row * N + n] =
                        __floats2bfloat162_rn(v0, v1);
                } else {
                    const float2 cv = *(const float2*)&((float*)C)[(size_t)row * N + n];
                    *(float2*)&((float*)C)[(size_t)row * N + n] =
                        make_float2(v0 + cv.x, v1 + cv.y);
                }
            }
        }
    }
}

// ---------------- windowed attention (writes bf16) ----------------
__global__ __launch_bounds__(256) void attn_kernel(
    const float* __restrict__ qkv, const float* __restrict__ rel_table,
    const int* __restrict__ rel_index, const float* __restrict__ mask,
    __nv_bfloat16* __restrict__ o)
{
    int w = blockIdx.x;
    int h = blockIdx.y;
    int widx = w & 63;
    int tid = threadIdx.x;

    __shared__ float q[NWIN][33], k[NWIN][33], v[NWIN][33];
    __shared__ float S[NWIN][NWIN];

    const float* base = qkv + (size_t)w * NWIN * (3 * CC) + h * HD;
    for (int e = tid; e < NWIN * HD; e += 256) {
        int i = e >> 5, d = e & 31;
        q[i][d] = base[i * (3 * CC) + d];
        k[i][d] = base[i * (3 * CC) + CC + d];
        v[i][d] = base[i * (3 * CC) + 2 * CC + d];
    }
    __syncthreads();

    for (int e = tid; e < NWIN * NWIN; e += 256) {
        int i = e / NWIN, j = e - i * NWIN;
        float s = 0.f;
        #pragma unroll
        for (int d = 0; d < HD; d++) s = fmaf(q[i][d], k[j][d], s);
        s += rel_table[rel_index[e] * NHD + h];
        s += mask[(size_t)widx * (NWIN * NWIN) + e];
        S[i][j] = s;
    }
    __syncthreads();

    int warp = tid >> 5, lane = tid & 31;
    for (int i = warp; i < NWIN; i += 8) {
        float a  = S[i][lane];
        float b2 = (lane + 32 < NWIN) ? S[i][lane + 32] : -1e30f;
        float mx = fmaxf(a, b2);
        #pragma unroll
        for (int off = 16; off; off >>= 1) mx = fmaxf(mx, __shfl_xor_sync(~0u, mx, off));
        float e1 = __expf(a - mx);
        float e2 = (lane + 32 < NWIN) ? __expf(b2 - mx) : 0.f;
        float sm = e1 + e2;
        #pragma unroll
        for (int off = 16; off; off >>= 1) sm += __shfl_xor_sync(~0u, sm, off);
        float inv = 1.f / sm;
        S[i][lane] = e1 * inv;
        if (lane + 32 < NWIN) S[i][lane + 32] = e2 * inv;
    }
    __syncthreads();

    __nv_bfloat16* orow = o + (size_t)w * NWIN * CC + h * HD;
    for (int e = tid; e < NWIN * HD; e += 256) {
        int i = e >> 5, d = e & 31;
        float s = 0.f;
        #pragma unroll
        for (int j = 0; j < NWIN; j++) s = fmaf(S[i][j], v[j][d], s);
        orow[i * CC + d] = __float2bfloat16(s);
    }
}

// ---------------- launch ----------------
extern "C" void kernel_launch(void* const* d_in, const int* in_sizes, int n_in,
                              void* d_out, int out_size) {
    const float* x        = (const float*)d_in[0];
    const float* norm1_g  = (const float*)d_in[1];
    const float* norm1_b  = (const float*)d_in[2];
    const float* qkv_w    = (const float*)d_in[3];
    const float* qkv_b    = (const float*)d_in[4];
    const float* proj_w   = (const float*)d_in[5];
    const float* proj_b   = (const float*)d_in[6];
    const float* norm2_g  = (const float*)d_in[7];
    const float* norm2_b  = (const float*)d_in[8];
    const float* fc1_w    = (const float*)d_in[9];
    const float* fc1_b    = (const float*)d_in[10];
    const float* fc2_w    = (const float*)d_in[11];
    const float* fc2_b    = (const float*)d_in[12];
    const float* rel_table= (const float*)d_in[13];
    const int*   rel_index= (const int*)  d_in[14];
    const float* mask     = (const float*)d_in[15];
    float* out = (float*)d_out;

    __nv_bfloat16 *xw, *o, *h1, *wq, *wp, *w1, *w2;
    float *qkv;
    cudaGetSymbolAddress((void**)&xw,  g_xw);
    cudaGetSymbolAddress((void**)&qkv, g_qkv);
    cudaGetSymbolAddress((void**)&o,   g_o);
    cudaGetSymbolAddress((void**)&h1,  g_h1);
    cudaGetSymbolAddress((void**)&wq,  g_wq);
    cudaGetSymbolAddress((void**)&wp,  g_wp);
    cudaGetSymbolAddress((void**)&w1,  g_w1);
    cudaGetSymbolAddress((void**)&w2,  g_w2);

    cvt_kernel<<<(CC*3*CC + 255) / 256, 256>>>(qkv_w,  wq, CC*3*CC);
    cvt_kernel<<<(CC*CC   + 255) / 256, 256>>>(proj_w, wp, CC*CC);
    cvt_kernel<<<(CC*HID  + 255) / 256, 256>>>(fc1_w,  w1, CC*HID);
    cvt_kernel<<<(HID*CC  + 255) / 256, 256>>>(fc2_w,  w2, HID*CC);

    ln_kernel<true><<<MROWS, CC>>>(x, norm1_g, norm1_b, xw);
    gemm_tc<0, float><<<dim3((3*CC)/GBN, MROWS/GBM), 256>>>(
        xw, wq, qkv_b, qkv, MROWS, 3*CC, CC, nullptr);
    attn_kernel<<<dim3(BW, NHD), 256>>>(qkv, rel_table, rel_index, mask, o);
    gemm_tc<1, float><<<dim3(CC/GBN, MROWS/GBM), 256>>>(
        o, wp, proj_b, out, MROWS, CC, CC, x);
    ln_kernel<false><<<MROWS, CC>>>(out, norm2_g, norm2_b, xw);
    gemm_tc<2, __nv_bfloat16><<<dim3(HID/GBN, MROWS/GBM), 256>>>(
        xw, w1, fc1_b, h1, MROWS, HID, CC, nullptr);
    gemm_tc<3, float><<<dim3(CC/GBN, MROWS/GBM), 256>>>(
        h1, w2, fc2_b, out, MROWS, CC, HID, nullptr);
}

// round 6
// speedup vs baseline: 3.9751x; 1.3726x over previous
#include <cuda_runtime.h>
#include <cuda_bf16.h>
#include <cstdint>

// ---------------- problem constants ----------------
#define BB   32
#define HH   56
#define CC   192
#define LL   (HH*HH)
#define NHD  6
#define HD   32
#define WSZ  7
#define SSH  3
#define NWIN 49
#define BW   2048
#define MROWS (BW*NWIN)        // 100352
#define HID  768
#define QSCALE 0.17677669529663687f

// ---------------- scratch ----------------
__device__ __nv_bfloat16 g_xw [(size_t)MROWS*CC];
__device__ __nv_bfloat16 g_qkv[(size_t)MROWS*3*CC];
__device__ __nv_bfloat16 g_o  [(size_t)MROWS*CC];
__device__ __nv_bfloat16 g_h1 [(size_t)MROWS*HID];
__device__ __nv_bfloat16 g_wq [(size_t)CC*3*CC];
__device__ __nv_bfloat16 g_wp [(size_t)CC*CC];
__device__ __nv_bfloat16 g_w1 [(size_t)CC*HID];
__device__ __nv_bfloat16 g_w2 [(size_t)HID*CC];

__device__ __forceinline__ int remap_row(int m) {
    int w = m / NWIN, n = m - w * NWIN;
    int b = w >> 6, widx = w & 63;
    int wi = widx >> 3, wj = widx & 7;
    int ti = n / WSZ, tj = n - ti * WSZ;
    int i0 = wi * WSZ + ti + SSH; if (i0 >= HH) i0 -= HH;
    int j0 = wj * WSZ + tj + SSH; if (j0 >= HH) j0 -= HH;
    return b * LL + i0 * HH + j0;
}

// ---------------- weight f32 -> bf16 ----------------
__global__ void cvt_kernel(const float* __restrict__ s, __nv_bfloat16* __restrict__ d, int n) {
    int i = blockIdx.x * 256 + threadIdx.x;
    if (i < n) d[i] = __float2bfloat16(s[i]);
}

// ---------------- LayerNorm (writes bf16) ----------------
template<bool GATHER>
__global__ void ln_kernel(const float* __restrict__ x, const float* __restrict__ g,
                          const float* __restrict__ b, __nv_bfloat16* __restrict__ y) {
    int m = blockIdx.x;
    int r = GATHER ? remap_row(m) : m;
    int tid = threadIdx.x;
    float val = x[(size_t)r * CC + tid];
    float s = val, s2 = val * val;
    #pragma unroll
    for (int off = 16; off; off >>= 1) {
        s  += __shfl_xor_sync(~0u, s,  off);
        s2 += __shfl_xor_sync(~0u, s2, off);
    }
    __shared__ float red[12];
    int warp = tid >> 5, lane = tid & 31;
    if (lane == 0) { red[warp] = s; red[6 + warp] = s2; }
    __syncthreads();
    if (tid < 32) {
        float a = (tid < 6) ? red[tid]     : 0.f;
        float c = (tid < 6) ? red[6 + tid] : 0.f;
        #pragma unroll
        for (int off = 4; off; off >>= 1) {
            a += __shfl_xor_sync(~0u, a, off);
            c += __shfl_xor_sync(~0u, c, off);
        }
        if (tid == 0) { red[0] = a; red[1] = c; }
    }
    __syncthreads();
    float mean = red[0] * (1.f / CC);
    float var  = red[1] * (1.f / CC) - mean * mean;
    float inv  = rsqrtf(var + 1e-5f);
    y[(size_t)m * CC + tid] = __float2bfloat16((val - mean) * inv * g[tid] + b[tid]);
}

// ---------------- shared mma/ldsm helpers ----------------
__device__ __forceinline__ void ldsm_x4(uint32_t& r0, uint32_t& r1, uint32_t& r2,
                                        uint32_t& r3, uint32_t a) {
    asm volatile("ldmatrix.sync.aligned.m8n8.x4.shared.b16 {%0,%1,%2,%3}, [%4];"
                 : "=r"(r0), "=r"(r1), "=r"(r2), "=r"(r3) : "r"(a));
}
__device__ __forceinline__ void ldsm_x4t(uint32_t& r0, uint32_t& r1, uint32_t& r2,
                                         uint32_t& r3, uint32_t a) {
    asm volatile("ldmatrix.sync.aligned.m8n8.x4.trans.shared.b16 {%0,%1,%2,%3}, [%4];"
                 : "=r"(r0), "=r"(r1), "=r"(r2), "=r"(r3) : "r"(a));
}
__device__ __forceinline__ void mma_bf16(float* d, uint32_t a0, uint32_t a1,
                                         uint32_t a2, uint32_t a3,
                                         uint32_t b0, uint32_t b1) {
    asm volatile(
        "mma.sync.aligned.m16n8k16.row.col.f32.bf16.bf16.f32 "
        "{%0,%1,%2,%3}, {%4,%5,%6,%7}, {%8,%9}, {%0,%1,%2,%3};"
        : "+f"(d[0]), "+f"(d[1]), "+f"(d[2]), "+f"(d[3])
        : "r"(a0), "r"(a1), "r"(a2), "r"(a3), "r"(b0), "r"(b1));
}

// ---------------- bf16 GEMM: cp.async + ldmatrix + 3-stage pipeline ------
#define GBM 128
#define GBN 64
#define AST 40
#define BST 72
#define STG_ELTS (128*AST + 32*BST)
#define NSTG 3

__device__ __forceinline__ void cp16(uint32_t saddr, const void* g) {
    asm volatile("cp.async.cg.shared.global [%0], [%1], 16;" :: "r"(saddr), "l"(g));
}
#define CP_COMMIT() asm volatile("cp.async.commit_group;")
#define CP_WAIT1()  asm volatile("cp.async.wait_group 1;")

template<int EPI, typename TOut>
__global__ __launch_bounds__(256) void gemm_tc(
    const __nv_bfloat16* __restrict__ A, const __nv_bfloat16* __restrict__ B,
    const float* __restrict__ bias, TOut* __restrict__ C,
    int M, int N, int K, const float* __restrict__ resid)
{
    __shared__ __align__(16) __nv_bfloat16 sm[NSTG * STG_ELTS];
    uint32_t sbase = (uint32_t)__cvta_generic_to_shared(sm);

    int bm = blockIdx.y * GBM, bn = blockIdx.x * GBN;
    int tid = threadIdx.x, lane = tid & 31;
    int lp = lane >> 2, lq = lane & 3;
    int warp = tid >> 5, wm = warp & 3, wn = warp >> 2;

    int a_r0 = tid >> 2;
    int a_c  = (tid & 3) * 8;
    int b_r  = tid >> 3;
    int b_c  = (tid & 7) * 8;
    int lrow = (lane & 7) + ((lane >> 3) & 1) * 8;
    int lcol = (lane >> 4) * 8;

    const int nk = K >> 5;
    float acc[2][4][4] = {};

    auto issue = [&](int it) {
        int s = it - (it / NSTG) * NSTG;
        uint32_t sa = sbase + (uint32_t)(s * STG_ELTS) * 2;
        int k0 = it << 5;
        cp16(sa + (uint32_t)(a_r0 * AST + a_c) * 2,
             A + (size_t)(bm + a_r0) * K + k0 + a_c);
        cp16(sa + (uint32_t)((a_r0 + 64) * AST + a_c) * 2,
             A + (size_t)(bm + a_r0 + 64) * K + k0 + a_c);
        cp16(sa + (uint32_t)(128 * AST + b_r * BST + b_c) * 2,
             B + (size_t)(k0 + b_r) * N + bn + b_c);
    };

    auto domma = [&](int it) {
        int s = it - (it / NSTG) * NSTG;
        uint32_t sa = sbase + (uint32_t)(s * STG_ELTS) * 2;
        uint32_t sb = sa + 128 * AST * 2;
        #pragma unroll
        for (int ks = 0; ks < 2; ks++) {
            uint32_t af[2][4], bfr[2][4];
            #pragma unroll
            for (int mt = 0; mt < 2; mt++)
                ldsm_x4(af[mt][0], af[mt][1], af[mt][2], af[mt][3],
                        sa + (uint32_t)((wm * 32 + mt * 16 + lrow) * AST + ks * 16 + lcol) * 2);
            #pragma unroll
            for (int g = 0; g < 2; g++)
                ldsm_x4t(bfr[g][0], bfr[g][1], bfr[g][2], bfr[g][3],
                         sb + (uint32_t)((ks * 16 + lrow) * BST + wn * 32 + g * 16 + lcol) * 2);
            #pragma unroll
            for (int mt = 0; mt < 2; mt++)
                #pragma unroll
                for (int nt = 0; nt < 4; nt++) {
                    int g = nt >> 1, h = nt & 1;
                    mma_bf16(acc[mt][nt], af[mt][0], af[mt][1], af[mt][2], af[mt][3],
                             bfr[g][h * 2], bfr[g][h * 2 + 1]);
                }
        }
    };

    issue(0); CP_COMMIT();
    issue(1); CP_COMMIT();
    for (int it = 0; it < nk; it++) {
        CP_WAIT1();
        __syncthreads();
        if (it + 2 < nk) issue(it + 2);
        CP_COMMIT();
        domma(it);
    }

    int m0 = wm * 32, n0 = wn * 32;
    #pragma unroll
    for (int mt = 0; mt < 2; mt++) {
        #pragma unroll
        for (int half = 0; half < 2; half++) {
            int m = bm + m0 + mt * 16 + lp + half * 8;
            int row = (EPI == 1) ? remap_row(m) : m;
            #pragma unroll
            for (int nt = 0; nt < 4; nt++) {
                int n = bn + n0 + nt * 8 + 2 * lq;
                float v0 = acc[mt][nt][half * 2 + 0] + bias[n];
                float v1 = acc[mt][nt][half * 2 + 1] + bias[n + 1];
                if constexpr (EPI == 0) {
                    if (n < CC) { v0 *= QSCALE; v1 *= QSCALE; }
                    *(__nv_bfloat162*)&((__nv_bfloat16*)C)[(size_t)row * N + n] =
                        __floats2bfloat162_rn(v0, v1);
                } else if constexpr (EPI == 1) {
                    const float2 rv = *(const float2*)&resid[(size_t)row * N + n];
                    *(float2*)&((float*)C)[(size_t)row * N + n] =
                        make_float2(v0 + rv.x, v1 + rv.y);
                } else if constexpr (EPI == 2) {
                    v0 = 0.5f * v0 * (1.f + erff(v0 * 0.70710678118654752f));
                    v1 = 0.5f * v1 * (1.f + erff(v1 * 0.70710678118654752f));
                    *(__nv_bfloat162*)&((__nv_bfloat16*)C)[(size_t)row * N + n] =
                        __floats2bfloat162_rn(v0, v1);
                } else {
                    const float2 cv = *(const float2*)&((float*)C)[(size_t)row * N + n];
                    *(float2*)&((float*)C)[(size_t)row * N + n] =
                        make_float2(v0 + cv.x, v1 + cv.y);
                }
            }
        }
    }
}

// ---------------- tensor-core windowed attention ----------------
// one block per (window, head); 4 warps; 49 padded to 64.
#define NP  64
#define QST 40      // Q/K/V smem stride (bf16): 80B, ldsm conflict-free
#define PST 72      // P smem stride: 144B, ldsm conflict-free

__global__ __launch_bounds__(128) void attn_tc(
    const __nv_bfloat16* __restrict__ qkv, const float* __restrict__ rel_table,
    const int* __restrict__ rel_index, const float* __restrict__ mask,
    __nv_bfloat16* __restrict__ o)
{
    __shared__ __align__(16) __nv_bfloat16 sQ[NP * QST];
    __shared__ __align__(16) __nv_bfloat16 sK[NP * QST];
    __shared__ __align__(16) __nv_bfloat16 sV[NP * QST];
    __shared__ __align__(16) __nv_bfloat16 sP[NP * PST];
    __shared__ float sBM[64 * 64];

    int w = blockIdx.x, h = blockIdx.y, widx = w & 63;
    int tid = threadIdx.x, lane = tid & 31, warp = tid >> 5;
    int lp = lane >> 2, lq = lane & 3;
    int lrow = (lane & 7) + ((lane >> 3) & 1) * 8;
    int lcol = (lane >> 4) * 8;

    // load Q,K,V (49x32 bf16 each, zero-pad to 64 rows)
    const __nv_bfloat16* qbase = qkv + (size_t)(w * NWIN) * (3 * CC) + h * HD;
    for (int idx = tid; idx < 3 * 64 * 4; idx += 128) {
        int t   = idx >> 8;          // tensor 0..2
        int row = (idx >> 2) & 63;
        int ch  = idx & 3;
        uint4 val = make_uint4(0, 0, 0, 0);
        if (row < NWIN)
            val = *(const uint4*)(qbase + (size_t)row * (3 * CC) + t * CC + ch * 8);
        __nv_bfloat16* dst = (t == 0) ? sQ : (t == 1) ? sK : sV;
        *(uint4*)(dst + row * QST + ch * 8) = val;
    }
    // combined bias + mask, padded with -1e30
    for (int e = tid; e < 64 * 64; e += 128) {
        int i = e >> 6, j = e & 63;
        float v = -1e30f;
        if (i < NWIN && j < NWIN)
            v = rel_table[rel_index[i * NWIN + j] * NHD + h]
              + mask[(size_t)widx * (NWIN * NWIN) + i * NWIN + j];
        sBM[e] = v;
    }
    __syncthreads();

    uint32_t qb = (uint32_t)__cvta_generic_to_shared(sQ);
    uint32_t kb = (uint32_t)__cvta_generic_to_shared(sK);
    uint32_t vb = (uint32_t)__cvta_generic_to_shared(sV);
    uint32_t pb = (uint32_t)__cvta_generic_to_shared(sP);

    // ---- S = Q @ K^T : warp computes rows [warp*16, +16) x 64 cols ----
    float S[8][4] = {};
    #pragma unroll
    for (int ks = 0; ks < 2; ks++) {
        uint32_t a0, a1, a2, a3;
        ldsm_x4(a0, a1, a2, a3,
                qb + (uint32_t)((warp * 16 + lrow) * QST + ks * 16 + lcol) * 2);
        #pragma unroll
        for (int g = 0; g < 4; g++) {
            uint32_t r0, r1, r2, r3;
            ldsm_x4(r0, r1, r2, r3,
                    kb + (uint32_t)((g * 16 + lrow) * QST + ks * 16 + lcol) * 2);
            mma_bf16(S[g * 2],     a0, a1, a2, a3, r0, r2);
            mma_bf16(S[g * 2 + 1], a0, a1, a2, a3, r1, r3);
        }
    }

    // ---- bias/mask + softmax (rows i0 = warp*16+lp and i0+8) ----
    int i0 = warp * 16 + lp;
    float mx0 = -1e30f, mx1 = -1e30f;
    #pragma unroll
    for (int nt = 0; nt < 8; nt++) {
        int c = nt * 8 + 2 * lq;
        S[nt][0] += sBM[i0 * 64 + c];
        S[nt][1] += sBM[i0 * 64 + c + 1];
        S[nt][2] += sBM[(i0 + 8) * 64 + c];
        S[nt][3] += sBM[(i0 + 8) * 64 + c + 1];
        mx0 = fmaxf(mx0, fmaxf(S[nt][0], S[nt][1]));
        mx1 = fmaxf(mx1, fmaxf(S[nt][2], S[nt][3]));
    }
    mx0 = fmaxf(mx0, __shfl_xor_sync(~0u, mx0, 1));
    mx0 = fmaxf(mx0, __shfl_xor_sync(~0u, mx0, 2));
    mx1 = fmaxf(mx1, __shfl_xor_sync(~0u, mx1, 1));
    mx1 = fmaxf(mx1, __shfl_xor_sync(~0u, mx1, 2));
    float sm0 = 0.f, sm1 = 0.f;
    #pragma unroll
    for (int nt = 0; nt < 8; nt++) {
        S[nt][0] = __expf(S[nt][0] - mx0);
        S[nt][1] = __expf(S[nt][1] - mx0);
        S[nt][2] = __expf(S[nt][2] - mx1);
        S[nt][3] = __expf(S[nt][3] - mx1);
        sm0 += S[nt][0] + S[nt][1];
        sm1 += S[nt][2] + S[nt][3];
    }
    sm0 += __shfl_xor_sync(~0u, sm0, 1);
    sm0 += __shfl_xor_sync(~0u, sm0, 2);
    sm1 += __shfl_xor_sync(~0u, sm1, 1);
    sm1 += __shfl_xor_sync(~0u, sm1, 2);
    float inv0 = 1.f / sm0, inv1 = 1.f / sm1;
    #pragma unroll
    for (int nt = 0; nt < 8; nt++) {
        int c = nt * 8 + 2 * lq;
        *(__nv_bfloat162*)(sP + i0 * PST + c) =
            __floats2bfloat162_rn(S[nt][0] * inv0, S[nt][1] * inv0);
        *(__nv_bfloat162*)(sP + (i0 + 8) * PST + c) =
            __floats2bfloat162_rn(S[nt][2] * inv1, S[nt][3] * inv1);
    }
    __syncwarp();

    // ---- O = P @ V : rows [warp*16,+16) x 32 cols, K = 64 ----
    float O[4][4] = {};
    #pragma unroll
    for (int kst = 0; kst < 4; kst++) {
        uint32_t a0, a1, a2, a3;
        ldsm_x4(a0, a1, a2, a3,
                pb + (uint32_t)((warp * 16 + lrow) * PST + kst * 16 + lcol) * 2);
        #pragma unroll
        for (int g = 0; g < 2; g++) {
            uint32_t r0, r1, r2, r3;
            ldsm_x4t(r0, r1, r2, r3,
                     vb + (uint32_t)((kst * 16 + lrow) * QST + g * 16 + lcol) * 2);
            mma_bf16(O[g * 2],     a0, a1, a2, a3, r0, r1);
            mma_bf16(O[g * 2 + 1], a0, a1, a2, a3, r2, r3);
        }
    }

    // ---- write O (bf16) into window layout ----
    __nv_bfloat16* obase = o + (size_t)(w * NWIN) * CC + h * HD;
    #pragma unroll
    for (int half = 0; half < 2; half++) {
        int i = i0 + half * 8;
        if (i < NWIN) {
            #pragma unroll
            for (int nt = 0; nt < 4; nt++) {
                int d = nt * 8 + 2 * lq;
                *(__nv_bfloat162*)(obase + (size_t)i * CC + d) =
                    __floats2bfloat162_rn(O[nt][half * 2], O[nt][half * 2 + 1]);
            }
        }
    }
}

// ---------------- launch ----------------
extern "C" void kernel_launch(void* const* d_in, const int* in_sizes, int n_in,
                              void* d_out, int out_size) {
    const float* x        = (const float*)d_in[0];
    const float* norm1_g  = (const float*)d_in[1];
    const float* norm1_b  = (const float*)d_in[2];
    const float* qkv_w    = (const float*)d_in[3];
    const float* qkv_b    = (const float*)d_in[4];
    const float* proj_w   = (const float*)d_in[5];
    const float* proj_b   = (const float*)d_in[6];
    const float* norm2_g  = (const float*)d_in[7];
    const float* norm2_b  = (const float*)d_in[8];
    const float* fc1_w    = (const float*)d_in[9];
    const float* fc1_b    = (const float*)d_in[10];
    const float* fc2_w    = (const float*)d_in[11];
    const float* fc2_b    = (const float*)d_in[12];
    const float* rel_table= (const float*)d_in[13];
    const int*   rel_index= (const int*)  d_in[14];
    const float* mask     = (const float*)d_in[15];
    float* out = (float*)d_out;

    __nv_bfloat16 *xw, *qkv, *o, *h1, *wq, *wp, *w1, *w2;
    cudaGetSymbolAddress((void**)&xw,  g_xw);
    cudaGetSymbolAddress((void**)&qkv, g_qkv);
    cudaGetSymbolAddress((void**)&o,   g_o);
    cudaGetSymbolAddress((void**)&h1,  g_h1);
    cudaGetSymbolAddress((void**)&wq,  g_wq);
    cudaGetSymbolAddress((void**)&wp,  g_wp);
    cudaGetSymbolAddress((void**)&w1,  g_w1);
    cudaGetSymbolAddress((void**)&w2,  g_w2);

    cvt_kernel<<<(CC*3*CC + 255) / 256, 256>>>(qkv_w,  wq, CC*3*CC);
    cvt_kernel<<<(CC*CC   + 255) / 256, 256>>>(proj_w, wp, CC*CC);
    cvt_kernel<<<(CC*HID  + 255) / 256, 256>>>(fc1_w,  w1, CC*HID);
    cvt_kernel<<<(HID*CC  + 255) / 256, 256>>>(fc2_w,  w2, HID*CC);

    ln_kernel<true><<<MROWS, CC>>>(x, norm1_g, norm1_b, xw);
    gemm_tc<0, __nv_bfloat16><<<dim3((3*CC)/GBN, MROWS/GBM), 256>>>(
        xw, wq, qkv_b, qkv, MROWS, 3*CC, CC, nullptr);
    attn_tc<<<dim3(BW, NHD), 128>>>(qkv, rel_table, rel_index, mask, o);
    gemm_tc<1, float><<<dim3(CC/GBN, MROWS/GBM), 256>>>(
        o, wp, proj_b, out, MROWS, CC, CC, x);
    ln_kernel<false><<<MROWS, CC>>>(out, norm2_g, norm2_b, xw);
    gemm_tc<2, __nv_bfloat16><<<dim3(HID/GBN, MROWS/GBM), 256>>>(
        xw, w1, fc1_b, h1, MROWS, HID, CC, nullptr);
    gemm_tc<3, float><<<dim3(CC/GBN, MROWS/GBM), 256>>>(
        h1, w2, fc2_b, out, MROWS, CC, HID, nullptr);
}